// round 1
// baseline (speedup 1.0000x reference)
#include <cuda_runtime.h>

#define STEPS   32
#define NTHETA  32
#define SPLITS  8
#define CELLS   (STEPS * NTHETA)   // 1024
#define MAXG    1024

// Per-graph start offsets into the sorted node array. g_start[g] = first node
// with index >= g; g_start[ngraph] = n. Recomputed every launch (deterministic).
__device__ int g_start[MAXG + 1];

// ---------------------------------------------------------------------------
// prep: zero the output and build g_start from the sorted index array.
// Handles both int32 and int64 index storage: for int64 (little-endian,
// values < 2^31, n even) the 32-bit word at position n-1 is a high word == 0;
// for int32 it is the last (max) graph index, which is > 0 w.p. ~1.
// ---------------------------------------------------------------------------
__global__ void prep_kernel(const int* __restrict__ idx32, int n,
                            float* __restrict__ out, int out_n, int ngraph) {
    int i = blockIdx.x * blockDim.x + threadIdx.x;
    if (i < out_n) out[i] = 0.0f;
    if (i >= n) return;

    const bool is64 = (idx32[n - 1] == 0);
    int a = is64 ? idx32[2 * i] : idx32[i];

    if (i == 0) {
        for (int g = 0; g <= a; ++g) g_start[g] = 0;
    } else {
        int b = is64 ? idx32[2 * (i - 1)] : idx32[i - 1];
        if (a != b)
            for (int g = b + 1; g <= a; ++g) g_start[g] = i;
    }
    if (i == n - 1) {
        for (int g = a + 1; g <= ngraph; ++g) g_start[g] = n;
    }
}

// ---------------------------------------------------------------------------
// main: per (graph, split) block. lane = theta (v column in registers),
// warp = node. Accumulate sigmoid INCREMENTS D[s] = sig(s) - sig(s-1) into a
// per-warp private [32 x 32] shared tile (lane-exclusive -> no atomics, no
// bank conflicts), then block-reduce and atomicAdd into global.
// ---------------------------------------------------------------------------
__global__ __launch_bounds__(256)
void main_kernel(const float* __restrict__ x, const float* __restrict__ v,
                 const float* __restrict__ lin, float* __restrict__ out) {
    __shared__ float D[8 * CELLS];      // 32 KB: one [STEPS][NTHETA] tile per warp
    __shared__ float lin_sh[STEPS];

    const int tid  = threadIdx.x;
    const int lane = tid & 31;
    const int warp = tid >> 5;

    if (tid < STEPS) lin_sh[tid] = lin[tid];
    for (int i = tid; i < 8 * CELLS; i += 256) D[i] = 0.0f;

    // v is [3, 32] row-major; this thread's theta column in registers.
    const float v0 = v[lane];
    const float v1 = v[NTHETA + lane];
    const float v2 = v[2 * NTHETA + lane];

    const int g  = blockIdx.y;
    const int s0 = g_start[g];
    const int s1 = g_start[g + 1];
    const int len = s1 - s0;
    const int beg = s0 + (int)(((long long)len * blockIdx.x) / SPLITS);
    const int end = s0 + (int)(((long long)len * (blockIdx.x + 1)) / SPLITS);

    __syncthreads();

    float* wD = D + warp * CELLS;
    const float INV_STEP = 31.0f / 2.2f;   // 1/delta
    const float W = 0.6f;                  // window half-width in step units
                                           // (|z| <= 500*delta*0.6 ~= 21.3; tail < 6e-10)

    for (int node = beg + warp; node < end; node += 8) {
        // All 32 lanes of this warp share one node -> broadcast loads.
        const float x0 = __ldg(x + 3 * node);
        const float x1 = __ldg(x + 3 * node + 1);
        const float x2 = __ldg(x + 3 * node + 2);
        const float nh = fmaf(x0, v0, fmaf(x1, v1, x2 * v2));

        const float p = (nh + 1.1f) * INV_STEP;       // real-valued step coord
        const int slo = (int)ceilf(p - W);
        const int shi = (int)floorf(p + W);           // slo <= shi always (2W > 1)
        int lo = slo < 0 ? 0 : slo;
        int hi = shi > (STEPS - 1) ? (STEPS - 1) : shi;

        float prev = 0.0f;                            // sigma below window ~ 0;
                                                      // also the s=0 cumsum baseline
        for (int s = lo; s <= hi; ++s) {              // at most 2 iterations
            float zneg = 500.0f * (nh - lin_sh[s]);   // -z, |.| <= ~21.6
            float sig  = __fdividef(1.0f, 1.0f + __expf(zneg));
            wD[s * NTHETA + lane] += sig - prev;
            prev = sig;
        }
        int st = shi + 1;                             // sigma == 1 from here on
        if (st < 0) st = 0;
        if (st < STEPS) wD[st * NTHETA + lane] += 1.0f - prev;
    }

    __syncthreads();

    // Reduce the 8 warp tiles and push increments to global.
    for (int c = tid; c < CELLS; c += 256) {
        float acc = 0.0f;
        #pragma unroll
        for (int w = 0; w < 8; ++w) acc += D[w * CELLS + c];
        if (acc != 0.0f) atomicAdd(out + g * CELLS + c, acc);
    }
}

// ---------------------------------------------------------------------------
// scan: in-place prefix sum over the step axis per (graph, theta).
// ---------------------------------------------------------------------------
__global__ void scan_kernel(float* __restrict__ out) {
    const int g = blockIdx.x;
    const int t = threadIdx.x;       // 32 threads = thetas, coalesced
    float* base = out + g * CELLS + t;
    float run = 0.0f;
    #pragma unroll
    for (int s = 0; s < STEPS; ++s) {
        run += base[s * NTHETA];
        base[s * NTHETA] = run;
    }
}

// ---------------------------------------------------------------------------
// Inputs (metadata order): x [N,3] f32, v [3,32] f32, lin [32] f32,
// index [N] int (32 or 64), (num_segments scalar, unused). Output f32
// [ngraph, 32, 32].
// ---------------------------------------------------------------------------
extern "C" void kernel_launch(void* const* d_in, const int* in_sizes, int n_in,
                              void* d_out, int out_size) {
    const float* x   = (const float*)d_in[0];
    const float* v   = (const float*)d_in[1];
    const float* lin = (const float*)d_in[2];
    const int*   idx = (const int*)d_in[3];
    float*       out = (float*)d_out;

    const int n      = in_sizes[3];                 // number of nodes
    const int ngraph = out_size / CELLS;            // 128

    const int cover = (n > out_size) ? n : out_size;
    const int prep_blocks = (cover + 255) / 256;
    prep_kernel<<<prep_blocks, 256>>>(idx, n, out, out_size, ngraph);

    dim3 grid(SPLITS, ngraph);
    main_kernel<<<grid, 256>>>(x, v, lin, out);

    scan_kernel<<<ngraph, 32>>>(out);
}